// round 1
// baseline (speedup 1.0000x reference)
#include <cuda_runtime.h>
#include <math.h>
#include <stdint.h>

// Problem constants
#define BB 8
#define LL 1024
#define DD 256
#define FF 11
#define TEMP_INV (1.0f/16.0f)
#define LN_EPS 1e-6f

// ---------------------------------------------------------------------------
// Scratch (static device globals; no allocation at runtime)
// ---------------------------------------------------------------------------
__device__ float g_qp [BB*LL*DD];
__device__ float g_kp [BB*LL*DD];
__device__ float g_vp [BB*LL*DD];
__device__ float g_q2 [BB*LL*DD];
__device__ float g_k2 [BB*LL*DD];
__device__ float g_q2f[BB*LL*DD];
__device__ float g_k2f[BB*LL*DD];
__device__ float g_ov [BB*LL*DD];
__device__ float g_fc [BB*LL*DD];
__device__ float g_fa [(size_t)BB*LL*LL];
__device__ float g_attn_scratch[(size_t)BB*LL*LL]; // used only if harness doesn't want attn output

// ---------------------------------------------------------------------------
// Generic 64x64x16 SGEMM, NT: C[m,n] = sum_k A[m,k] * W[n,k]  (+ optional add)
// A: [M,K] row-major, W: [N,K] row-major. M%64==0, N%64==0, K%16==0.
// grid: (N/64, M/64), block: 256
// ---------------------------------------------------------------------------
__global__ __launch_bounds__(256)
void gemm_nt(const float* __restrict__ A, const float* __restrict__ W,
             const float* __restrict__ add, float* __restrict__ C,
             int M, int N, int K)
{
    __shared__ float As[16][64];
    __shared__ float Bs[16][64];
    const int tid = threadIdx.x;
    const int tx = tid & 15, ty = tid >> 4;
    const int m0 = blockIdx.y * 64, n0 = blockIdx.x * 64;
    const int lr = tid >> 2;          // 0..63
    const int lc = (tid & 3) << 2;    // 0,4,8,12

    const float* Arow = A + (size_t)(m0 + lr) * K + lc;
    const float* Wrow = W + (size_t)(n0 + lr) * K + lc;

    float acc[4][4] = {};
    for (int k0 = 0; k0 < K; k0 += 16) {
        float4 a = *(const float4*)(Arow + k0);
        float4 b = *(const float4*)(Wrow + k0);
        As[lc+0][lr]=a.x; As[lc+1][lr]=a.y; As[lc+2][lr]=a.z; As[lc+3][lr]=a.w;
        Bs[lc+0][lr]=b.x; Bs[lc+1][lr]=b.y; Bs[lc+2][lr]=b.z; Bs[lc+3][lr]=b.w;
        __syncthreads();
        #pragma unroll
        for (int kk = 0; kk < 16; kk++) {
            float4 av = *(const float4*)&As[kk][ty<<2];
            float4 bv = *(const float4*)&Bs[kk][tx<<2];
            float ar[4] = {av.x, av.y, av.z, av.w};
            float br[4] = {bv.x, bv.y, bv.z, bv.w};
            #pragma unroll
            for (int i = 0; i < 4; i++)
                #pragma unroll
                for (int j = 0; j < 4; j++)
                    acc[i][j] += ar[i] * br[j];
        }
        __syncthreads();
    }
    #pragma unroll
    for (int i = 0; i < 4; i++) {
        int m = m0 + (ty<<2) + i;
        #pragma unroll
        for (int j = 0; j < 4; j++) {
            int n = n0 + (tx<<2) + j;
            float v = acc[i][j];
            if (add) v += add[(size_t)m*N + n];
            C[(size_t)m*N + n] = v;
        }
    }
}

// ---------------------------------------------------------------------------
// Batched NN GEMM: C[b,m,n] = sum_k A[b,m,k] * Bm[b,k,n]
// grid: (N/64, M/64, batch)
// ---------------------------------------------------------------------------
__global__ __launch_bounds__(256)
void bgemm_nn(const float* __restrict__ A, const float* __restrict__ Bm,
              float* __restrict__ C, int M, int N, int K,
              size_t sA, size_t sB, size_t sC)
{
    const int b = blockIdx.z;
    A += (size_t)b * sA; Bm += (size_t)b * sB; C += (size_t)b * sC;

    __shared__ float As[16][64];
    __shared__ float Bs[16][64];
    const int tid = threadIdx.x;
    const int tx = tid & 15, ty = tid >> 4;
    const int m0 = blockIdx.y * 64, n0 = blockIdx.x * 64;
    const int lr = tid >> 2;
    const int lc = (tid & 3) << 2;
    const int kb = tid >> 4;           // 0..15
    const int nb = (tid & 15) << 2;    // 0..60

    const float* Arow = A + (size_t)(m0 + lr) * K + lc;
    const float* Brow = Bm + (size_t)kb * N + n0 + nb;

    float acc[4][4] = {};
    for (int k0 = 0; k0 < K; k0 += 16) {
        float4 a = *(const float4*)(Arow + k0);
        float4 bv = *(const float4*)(Brow + (size_t)k0 * N);
        As[lc+0][lr]=a.x; As[lc+1][lr]=a.y; As[lc+2][lr]=a.z; As[lc+3][lr]=a.w;
        *(float4*)&Bs[kb][nb] = bv;
        __syncthreads();
        #pragma unroll
        for (int kk = 0; kk < 16; kk++) {
            float4 av = *(const float4*)&As[kk][ty<<2];
            float4 b4 = *(const float4*)&Bs[kk][tx<<2];
            float ar[4] = {av.x, av.y, av.z, av.w};
            float br[4] = {b4.x, b4.y, b4.z, b4.w};
            #pragma unroll
            for (int i = 0; i < 4; i++)
                #pragma unroll
                for (int j = 0; j < 4; j++)
                    acc[i][j] += ar[i] * br[j];
        }
        __syncthreads();
    }
    #pragma unroll
    for (int i = 0; i < 4; i++) {
        int m = m0 + (ty<<2) + i;
        #pragma unroll
        for (int j = 0; j < 4; j++)
            C[(size_t)m*N + n0 + (tx<<2) + j] = acc[i][j];
    }
}

// ---------------------------------------------------------------------------
// Dual batched NN GEMM: shares A tile, two B inputs / two C outputs.
// C1 = fa @ q2, C2 = fa @ k2. grid: (N/64, M/64, batch)
// ---------------------------------------------------------------------------
__global__ __launch_bounds__(256)
void dual_bgemm_nn(const float* __restrict__ A,
                   const float* __restrict__ B1, const float* __restrict__ B2,
                   float* __restrict__ C1, float* __restrict__ C2,
                   int M, int N, int K, size_t sA, size_t sB, size_t sC)
{
    const int b = blockIdx.z;
    A += (size_t)b * sA;
    B1 += (size_t)b * sB; B2 += (size_t)b * sB;
    C1 += (size_t)b * sC; C2 += (size_t)b * sC;

    __shared__ float As[16][64];
    __shared__ float Bs1[16][64];
    __shared__ float Bs2[16][64];
    const int tid = threadIdx.x;
    const int tx = tid & 15, ty = tid >> 4;
    const int m0 = blockIdx.y * 64, n0 = blockIdx.x * 64;
    const int lr = tid >> 2;
    const int lc = (tid & 3) << 2;
    const int kb = tid >> 4;
    const int nb = (tid & 15) << 2;

    const float* Arow = A + (size_t)(m0 + lr) * K + lc;
    const float* B1row = B1 + (size_t)kb * N + n0 + nb;
    const float* B2row = B2 + (size_t)kb * N + n0 + nb;

    float acc1[4][4] = {}, acc2[4][4] = {};
    for (int k0 = 0; k0 < K; k0 += 16) {
        float4 a  = *(const float4*)(Arow + k0);
        float4 b1 = *(const float4*)(B1row + (size_t)k0 * N);
        float4 b2 = *(const float4*)(B2row + (size_t)k0 * N);
        As[lc+0][lr]=a.x; As[lc+1][lr]=a.y; As[lc+2][lr]=a.z; As[lc+3][lr]=a.w;
        *(float4*)&Bs1[kb][nb] = b1;
        *(float4*)&Bs2[kb][nb] = b2;
        __syncthreads();
        #pragma unroll
        for (int kk = 0; kk < 16; kk++) {
            float4 av  = *(const float4*)&As[kk][ty<<2];
            float4 bv1 = *(const float4*)&Bs1[kk][tx<<2];
            float4 bv2 = *(const float4*)&Bs2[kk][tx<<2];
            float ar[4]  = {av.x, av.y, av.z, av.w};
            float br1[4] = {bv1.x, bv1.y, bv1.z, bv1.w};
            float br2[4] = {bv2.x, bv2.y, bv2.z, bv2.w};
            #pragma unroll
            for (int i = 0; i < 4; i++)
                #pragma unroll
                for (int j = 0; j < 4; j++) {
                    acc1[i][j] += ar[i] * br1[j];
                    acc2[i][j] += ar[i] * br2[j];
                }
        }
        __syncthreads();
    }
    #pragma unroll
    for (int i = 0; i < 4; i++) {
        int m = m0 + (ty<<2) + i;
        #pragma unroll
        for (int j = 0; j < 4; j++) {
            int n = n0 + (tx<<2) + j;
            C1[(size_t)m*N + n] = acc1[i][j];
            C2[(size_t)m*N + n] = acc2[i][j];
        }
    }
}

// ---------------------------------------------------------------------------
// fa kernel: one block per (b, i) row of the feature-affinity softmax.
// fa[b,i,j] = softmax_j( mask(j) ? sum_f |x[b,i,f]-x[b,j,f]| * fi[f] : -inf )
// ---------------------------------------------------------------------------
__global__ __launch_bounds__(256)
void fa_kernel(const float* __restrict__ x, const float* __restrict__ fi,
               const int* __restrict__ lens, float* __restrict__ fa)
{
    const int bi = blockIdx.x;
    const int b = bi >> 10, i = bi & 1023;
    const int t = threadIdx.x;

    __shared__ float xi[FF], fis[FF];
    __shared__ float red[256];
    if (t < FF) {
        xi[t]  = x[((size_t)b*LL + i)*FF + t];
        fis[t] = fi[t];
    }
    __syncthreads();
    const int len = lens[b];

    float vals[4];
    #pragma unroll
    for (int r = 0; r < 4; r++) {
        int j = t + r*256;
        const float* xj = x + ((size_t)b*LL + j)*FF;
        float s = 0.f;
        #pragma unroll
        for (int f = 0; f < FF; f++) s += fabsf(xi[f] - xj[f]) * fis[f];
        vals[r] = (j < len) ? s : -INFINITY;
    }
    // row max
    float m = fmaxf(fmaxf(vals[0], vals[1]), fmaxf(vals[2], vals[3]));
    red[t] = m; __syncthreads();
    for (int s = 128; s > 0; s >>= 1) {
        if (t < s) red[t] = fmaxf(red[t], red[t+s]);
        __syncthreads();
    }
    const float rowmax = red[0];
    __syncthreads();
    // exp + sum
    float e[4], lsum = 0.f;
    #pragma unroll
    for (int r = 0; r < 4; r++) { e[r] = expf(vals[r] - rowmax); lsum += e[r]; }
    red[t] = lsum; __syncthreads();
    for (int s = 128; s > 0; s >>= 1) {
        if (t < s) red[t] += red[t+s];
        __syncthreads();
    }
    const float inv = 1.0f / red[0];
    float* out = fa + ((size_t)b*LL + i)*LL;
    #pragma unroll
    for (int r = 0; r < 4; r++) out[t + r*256] = e[r] * inv;
}

// ---------------------------------------------------------------------------
// logits kernel: attn[b,i,j] = (j<len) ? tanh((qp_i.kp_j + q2f_i.k2f_j)/16) : 0
// Two NT K=256 passes fused. grid: (L/64, L/64, B)
// ---------------------------------------------------------------------------
__global__ __launch_bounds__(256)
void logits_kernel(const float* __restrict__ qp, const float* __restrict__ kp,
                   const float* __restrict__ q2f, const float* __restrict__ k2f,
                   const int* __restrict__ lens, float* __restrict__ attn)
{
    const int b = blockIdx.z;
    const size_t od = (size_t)b * LL * DD;
    const float* A1 = qp + od;  const float* W1 = kp + od;
    const float* A2 = q2f + od; const float* W2 = k2f + od;
    float* out = attn + (size_t)b * LL * LL;
    const int len = lens[b];

    __shared__ float As[16][64];
    __shared__ float Bs[16][64];
    const int tid = threadIdx.x;
    const int tx = tid & 15, ty = tid >> 4;
    const int m0 = blockIdx.y * 64, n0 = blockIdx.x * 64;
    const int lr = tid >> 2;
    const int lc = (tid & 3) << 2;

    float acc[4][4] = {};
    #pragma unroll 1
    for (int pass = 0; pass < 2; pass++) {
        const float* A = pass ? A2 : A1;
        const float* W = pass ? W2 : W1;
        const float* Arow = A + (size_t)(m0 + lr) * DD + lc;
        const float* Wrow = W + (size_t)(n0 + lr) * DD + lc;
        for (int k0 = 0; k0 < DD; k0 += 16) {
            float4 a = *(const float4*)(Arow + k0);
            float4 bv = *(const float4*)(Wrow + k0);
            As[lc+0][lr]=a.x; As[lc+1][lr]=a.y; As[lc+2][lr]=a.z; As[lc+3][lr]=a.w;
            Bs[lc+0][lr]=bv.x; Bs[lc+1][lr]=bv.y; Bs[lc+2][lr]=bv.z; Bs[lc+3][lr]=bv.w;
            __syncthreads();
            #pragma unroll
            for (int kk = 0; kk < 16; kk++) {
                float4 av = *(const float4*)&As[kk][ty<<2];
                float4 b4 = *(const float4*)&Bs[kk][tx<<2];
                float ar[4] = {av.x, av.y, av.z, av.w};
                float br[4] = {b4.x, b4.y, b4.z, b4.w};
                #pragma unroll
                for (int i = 0; i < 4; i++)
                    #pragma unroll
                    for (int j = 0; j < 4; j++)
                        acc[i][j] += ar[i] * br[j];
            }
            __syncthreads();
        }
    }
    #pragma unroll
    for (int i = 0; i < 4; i++) {
        int m = m0 + (ty<<2) + i;
        #pragma unroll
        for (int j = 0; j < 4; j++) {
            int n = n0 + (tx<<2) + j;
            float v = (n < len) ? tanhf(acc[i][j] * TEMP_INV) : 0.0f;
            out[(size_t)m*LL + n] = v;
        }
    }
}

// ---------------------------------------------------------------------------
// LayerNorm: one block per row of 256.
// ---------------------------------------------------------------------------
__global__ __launch_bounds__(256)
void ln_kernel(const float* __restrict__ in, const float* __restrict__ gamma,
               const float* __restrict__ beta, float* __restrict__ out)
{
    const int row = blockIdx.x;
    const int t = threadIdx.x;
    __shared__ float red[256];
    const float v = in[(size_t)row*DD + t];
    red[t] = v; __syncthreads();
    for (int s = 128; s > 0; s >>= 1) {
        if (t < s) red[t] += red[t+s];
        __syncthreads();
    }
    const float mean = red[0] * (1.0f/DD);
    __syncthreads();
    const float d = v - mean;
    red[t] = d * d; __syncthreads();
    for (int s = 128; s > 0; s >>= 1) {
        if (t < s) red[t] += red[t+s];
        __syncthreads();
    }
    const float var = red[0] * (1.0f/DD);
    out[(size_t)row*DD + t] = d * rsqrtf(var + LN_EPS) * gamma[t] + beta[t];
}

// ---------------------------------------------------------------------------
// Host launch
// ---------------------------------------------------------------------------
extern "C" void kernel_launch(void* const* d_in, const int* in_sizes, int n_in,
                              void* d_out, int out_size)
{
    // Resolve input ordering: the size-8 tensor is inputs_lengths.
    int li = -1;
    for (int i = 0; i < n_in; i++) if (in_sizes[i] == BB) { li = i; break; }

    const float* q = (const float*)d_in[0];
    const float* k = (const float*)d_in[1];
    const float* v = (const float*)d_in[2];
    const float* x = (const float*)d_in[3];
    const int* lens;
    const float *w_qs, *w_ks, *w_vs, *w_qs2, *w_ks2, *w_fc, *fi, *gamma, *beta;
    if (li == 4) {   // setup_inputs dict order
        lens  = (const int*)d_in[4];
        w_qs  = (const float*)d_in[5];  w_ks  = (const float*)d_in[6];
        w_vs  = (const float*)d_in[7];  w_qs2 = (const float*)d_in[8];
        w_ks2 = (const float*)d_in[9];  w_fc  = (const float*)d_in[10];
        fi    = (const float*)d_in[11]; gamma = (const float*)d_in[12];
        beta  = (const float*)d_in[13];
    } else {         // reference signature order (lengths last)
        w_qs  = (const float*)d_in[4];  w_ks  = (const float*)d_in[5];
        w_vs  = (const float*)d_in[6];  w_qs2 = (const float*)d_in[7];
        w_ks2 = (const float*)d_in[8];  w_fc  = (const float*)d_in[9];
        fi    = (const float*)d_in[10]; gamma = (const float*)d_in[11];
        beta  = (const float*)d_in[12]; lens  = (const int*)d_in[13];
    }

    float *qp, *kp, *vp, *q2, *k2, *q2f, *k2f, *ov, *fc, *fa, *attn_scratch;
    cudaGetSymbolAddress((void**)&qp,  g_qp);
    cudaGetSymbolAddress((void**)&kp,  g_kp);
    cudaGetSymbolAddress((void**)&vp,  g_vp);
    cudaGetSymbolAddress((void**)&q2,  g_q2);
    cudaGetSymbolAddress((void**)&k2,  g_k2);
    cudaGetSymbolAddress((void**)&q2f, g_q2f);
    cudaGetSymbolAddress((void**)&k2f, g_k2f);
    cudaGetSymbolAddress((void**)&ov,  g_ov);
    cudaGetSymbolAddress((void**)&fc,  g_fc);
    cudaGetSymbolAddress((void**)&fa,  g_fa);
    cudaGetSymbolAddress((void**)&attn_scratch, g_attn_scratch);

    const size_t OUT_ELEMS  = (size_t)BB*LL*DD;
    const size_t ATTN_ELEMS = (size_t)BB*LL*LL;
    // attn is the 2nd tuple output; write into d_out if the harness sized for it.
    float* attn = ((size_t)out_size >= OUT_ELEMS + ATTN_ELEMS)
                ? (float*)d_out + OUT_ELEMS
                : attn_scratch;

    const int M = BB * LL;  // 8192

    dim3 blk(256);
    dim3 gproj(DD/64, M/64);               // 4 x 128
    // Projections
    gemm_nt<<<gproj, blk>>>(q, w_qs,  nullptr, qp, M, DD, DD);
    gemm_nt<<<gproj, blk>>>(k, w_ks,  nullptr, kp, M, DD, DD);
    gemm_nt<<<gproj, blk>>>(v, w_vs,  nullptr, vp, M, DD, DD);
    gemm_nt<<<gproj, blk>>>(q, w_qs2, nullptr, q2, M, DD, DD);
    gemm_nt<<<gproj, blk>>>(k, w_ks2, nullptr, k2, M, DD, DD);

    // Feature-affinity softmax
    fa_kernel<<<M, blk>>>(x, fi, lens, fa);

    // q2f = fa @ q2, k2f = fa @ k2
    dim3 gdual(DD/64, LL/64, BB);          // 4 x 16 x 8
    dual_bgemm_nn<<<gdual, blk>>>(fa, q2, k2, q2f, k2f,
                                  LL, DD, LL,
                                  (size_t)LL*LL, (size_t)LL*DD, (size_t)LL*DD);

    // attn logits + mask + tanh
    dim3 glog(LL/64, LL/64, BB);           // 16 x 16 x 8
    logits_kernel<<<glog, blk>>>(qp, kp, q2f, k2f, lens, attn);

    // out = attn @ vp
    dim3 gov(DD/64, LL/64, BB);
    bgemm_nn<<<gov, blk>>>(attn, vp, ov, LL, DD, LL,
                           (size_t)LL*LL, (size_t)LL*DD, (size_t)LL*DD);

    // fc projection + residual, then layernorm into d_out
    gemm_nt<<<gproj, blk>>>(ov, w_fc, q, fc, M, DD, DD);
    ln_kernel<<<M, blk>>>(fc, gamma, beta, (float*)d_out);
}

// round 2
// speedup vs baseline: 1.2835x; 1.2835x over previous
#include <cuda_runtime.h>
#include <math.h>
#include <stdint.h>

// Problem constants
#define BB 8
#define LL 1024
#define DD 256
#define FF 11
#define TEMP_INV (1.0f/16.0f)
#define LN_EPS 1e-6f
#define SMS 132   // padded smem row stride (128 + 4) -> conflict-free transposed STS

// ---------------------------------------------------------------------------
// Scratch (static device globals; no allocation at runtime)
// ---------------------------------------------------------------------------
__device__ float g_qp [BB*LL*DD];
__device__ float g_kp [BB*LL*DD];
__device__ float g_vp [BB*LL*DD];
__device__ float g_q2 [BB*LL*DD];
__device__ float g_k2 [BB*LL*DD];
__device__ float g_q2f[BB*LL*DD];
__device__ float g_k2f[BB*LL*DD];
__device__ float g_ov [BB*LL*DD];
__device__ float g_fc [BB*LL*DD];
__device__ float g_fa [(size_t)BB*LL*LL];
__device__ float g_attn_scratch[(size_t)BB*LL*LL];

// ---------------------------------------------------------------------------
// 8x8 microkernel step over one 8-deep K slab in shared memory.
// ---------------------------------------------------------------------------
__device__ __forceinline__
void mk_step(const float (*__restrict__ As)[SMS], const float (*__restrict__ Bs)[SMS],
             int ty4, int tx4, float acc[8][8])
{
    #pragma unroll
    for (int kk = 0; kk < 8; kk++) {
        float4 a0 = *(const float4*)&As[kk][ty4];
        float4 a1 = *(const float4*)&As[kk][ty4 + 64];
        float4 b0 = *(const float4*)&Bs[kk][tx4];
        float4 b1 = *(const float4*)&Bs[kk][tx4 + 64];
        float ar[8] = {a0.x,a0.y,a0.z,a0.w,a1.x,a1.y,a1.z,a1.w};
        float br[8] = {b0.x,b0.y,b0.z,b0.w,b1.x,b1.y,b1.z,b1.w};
        #pragma unroll
        for (int i = 0; i < 8; i++)
            #pragma unroll
            for (int j = 0; j < 8; j++)
                acc[i][j] += ar[i] * br[j];
    }
}

// ---------------------------------------------------------------------------
// NT GEMM body: C[m,n] = sum_k A[m,k]*W[n,k] (+add), K param, N fixed 256.
// 128x128 tile, K-slab 8, double buffered. grid:(N/128, M/128), block 256.
// ---------------------------------------------------------------------------
__device__ __forceinline__
void gemm_nt_body(const float* __restrict__ A, const float* __restrict__ W,
                  const float* __restrict__ add, float* __restrict__ C, int K)
{
    __shared__ float As[2][8][SMS];
    __shared__ float Bs[2][8][SMS];
    const int tid = threadIdx.x;
    const int tx4 = (tid & 15) << 2;
    const int ty4 = (tid >> 4) << 2;
    const int m0 = blockIdx.y * 128, n0 = blockIdx.x * 128;
    const int lr = tid >> 1;        // 0..127
    const int lk = (tid & 1) << 2;  // 0 or 4

    const float* Aptr = A + (size_t)(m0 + lr) * K + lk;
    const float* Wptr = W + (size_t)(n0 + lr) * K + lk;

    float acc[8][8] = {};

    // preload tile 0
    {
        float4 a = *(const float4*)Aptr;
        float4 b = *(const float4*)Wptr;
        As[0][lk+0][lr]=a.x; As[0][lk+1][lr]=a.y; As[0][lk+2][lr]=a.z; As[0][lk+3][lr]=a.w;
        Bs[0][lk+0][lr]=b.x; Bs[0][lk+1][lr]=b.y; Bs[0][lk+2][lr]=b.z; Bs[0][lk+3][lr]=b.w;
    }
    __syncthreads();

    const int nTiles = K >> 3;
    int buf = 0;
    for (int t = 0; t < nTiles; t++) {
        float4 an, bn;
        const bool has = (t + 1 < nTiles);
        if (has) {
            an = *(const float4*)(Aptr + (t+1)*8);
            bn = *(const float4*)(Wptr + (t+1)*8);
        }
        mk_step(As[buf], Bs[buf], ty4, tx4, acc);
        if (has) {
            int nb = buf ^ 1;
            As[nb][lk+0][lr]=an.x; As[nb][lk+1][lr]=an.y; As[nb][lk+2][lr]=an.z; As[nb][lk+3][lr]=an.w;
            Bs[nb][lk+0][lr]=bn.x; Bs[nb][lk+1][lr]=bn.y; Bs[nb][lk+2][lr]=bn.z; Bs[nb][lk+3][lr]=bn.w;
            __syncthreads();
            buf = nb;
        }
    }

    #pragma unroll
    for (int i = 0; i < 8; i++) {
        int m = m0 + ty4 + (i & 3) + ((i >> 2) << 6);
        float4 v0 = make_float4(acc[i][0], acc[i][1], acc[i][2], acc[i][3]);
        float4 v1 = make_float4(acc[i][4], acc[i][5], acc[i][6], acc[i][7]);
        if (add) {
            float4 r0 = *(const float4*)(add + (size_t)m*256 + n0 + tx4);
            float4 r1 = *(const float4*)(add + (size_t)m*256 + n0 + 64 + tx4);
            v0.x+=r0.x; v0.y+=r0.y; v0.z+=r0.z; v0.w+=r0.w;
            v1.x+=r1.x; v1.y+=r1.y; v1.z+=r1.z; v1.w+=r1.w;
        }
        *(float4*)(C + (size_t)m*256 + n0 + tx4)      = v0;
        *(float4*)(C + (size_t)m*256 + n0 + 64 + tx4) = v1;
    }
}

// Fused 5-projection launch: z selects (A, W, C).
__global__ __launch_bounds__(256)
void proj_kernel(const float* __restrict__ q, const float* __restrict__ k,
                 const float* __restrict__ v,
                 const float* __restrict__ w_qs, const float* __restrict__ w_ks,
                 const float* __restrict__ w_vs, const float* __restrict__ w_qs2,
                 const float* __restrict__ w_ks2,
                 float* __restrict__ qp, float* __restrict__ kp, float* __restrict__ vp,
                 float* __restrict__ q2, float* __restrict__ k2)
{
    const float* A; const float* W; float* C;
    switch (blockIdx.z) {
        case 0:  A = q; W = w_qs;  C = qp; break;
        case 1:  A = k; W = w_ks;  C = kp; break;
        case 2:  A = v; W = w_vs;  C = vp; break;
        case 3:  A = q; W = w_qs2; C = q2; break;
        default: A = k; W = w_ks2; C = k2; break;
    }
    gemm_nt_body(A, W, nullptr, C, DD);
}

// fc projection + residual
__global__ __launch_bounds__(256)
void fc_kernel(const float* __restrict__ ov, const float* __restrict__ w_fc,
               const float* __restrict__ q, float* __restrict__ out)
{
    gemm_nt_body(ov, w_fc, q, out, DD);
}

// ---------------------------------------------------------------------------
// Batched NN GEMM body: C[m,n] = sum_k A[m,k]*B[k,n], K=1024, N=256, lda=1024.
// ---------------------------------------------------------------------------
__device__ __forceinline__
void bgemm_nn_body(const float* __restrict__ A, const float* __restrict__ Bm,
                   float* __restrict__ C)
{
    __shared__ float As[2][8][SMS];
    __shared__ float Bs[2][8][SMS];
    const int tid = threadIdx.x;
    const int tx4 = (tid & 15) << 2;
    const int ty4 = (tid >> 4) << 2;
    const int m0 = blockIdx.y * 128, n0 = blockIdx.x * 128;
    const int lr = tid >> 1;        // 0..127 (A rows)
    const int lk = (tid & 1) << 2;  // 0 or 4 (A k-cols)
    const int bkr = tid >> 5;       // 0..7   (B k-rows)
    const int bnc = (tid & 31) << 2;// 0..124 (B n-cols)

    const float* Aptr = A + (size_t)(m0 + lr) * LL + lk;
    const float* Bptr = Bm + (size_t)bkr * DD + n0 + bnc;

    float acc[8][8] = {};

    {
        float4 a = *(const float4*)Aptr;
        float4 b = *(const float4*)Bptr;
        As[0][lk+0][lr]=a.x; As[0][lk+1][lr]=a.y; As[0][lk+2][lr]=a.z; As[0][lk+3][lr]=a.w;
        *(float4*)&Bs[0][bkr][bnc] = b;
    }
    __syncthreads();

    const int nTiles = LL >> 3;  // 128
    int buf = 0;
    for (int t = 0; t < nTiles; t++) {
        float4 an, bn;
        const bool has = (t + 1 < nTiles);
        if (has) {
            an = *(const float4*)(Aptr + (t+1)*8);
            bn = *(const float4*)(Bptr + (size_t)(t+1)*8*DD);
        }
        mk_step(As[buf], Bs[buf], ty4, tx4, acc);
        if (has) {
            int nb = buf ^ 1;
            As[nb][lk+0][lr]=an.x; As[nb][lk+1][lr]=an.y; As[nb][lk+2][lr]=an.z; As[nb][lk+3][lr]=an.w;
            *(float4*)&Bs[nb][bkr][bnc] = bn;
            __syncthreads();
            buf = nb;
        }
    }

    #pragma unroll
    for (int i = 0; i < 8; i++) {
        int m = m0 + ty4 + (i & 3) + ((i >> 2) << 6);
        *(float4*)(C + (size_t)m*DD + n0 + tx4)      = make_float4(acc[i][0],acc[i][1],acc[i][2],acc[i][3]);
        *(float4*)(C + (size_t)m*DD + n0 + 64 + tx4) = make_float4(acc[i][4],acc[i][5],acc[i][6],acc[i][7]);
    }
}

// q2f = fa@q2, k2f = fa@k2 in one launch: z = b*2 + sel
__global__ __launch_bounds__(256)
void bgemm_dual_kernel(const float* __restrict__ fa,
                       const float* __restrict__ q2, const float* __restrict__ k2,
                       float* __restrict__ q2f, float* __restrict__ k2f)
{
    const int b = blockIdx.z >> 1;
    const int sel = blockIdx.z & 1;
    const float* A  = fa + (size_t)b * LL * LL;
    const float* Bm = (sel ? k2  : q2)  + (size_t)b * LL * DD;
    float*       C  = (sel ? k2f : q2f) + (size_t)b * LL * DD;
    bgemm_nn_body(A, Bm, C);
}

// out = attn @ vp : z = b
__global__ __launch_bounds__(256)
void bgemm_av_kernel(const float* __restrict__ attn, const float* __restrict__ vp,
                     float* __restrict__ ov)
{
    const int b = blockIdx.z;
    bgemm_nn_body(attn + (size_t)b * LL * LL,
                  vp   + (size_t)b * LL * DD,
                  ov   + (size_t)b * LL * DD);
}

// ---------------------------------------------------------------------------
// logits: attn[b,i,j] = (j<len) ? tanh((qp_i.kp_j + q2f_i.k2f_j)/16) : 0
// Two NT K=256 passes linearized into 64 K-slabs. grid:(8,8,B)
// ---------------------------------------------------------------------------
__global__ __launch_bounds__(256)
void logits_kernel(const float* __restrict__ qp, const float* __restrict__ kp,
                   const float* __restrict__ q2f, const float* __restrict__ k2f,
                   const int* __restrict__ lens, float* __restrict__ attn)
{
    const int b = blockIdx.z;
    const size_t od = (size_t)b * LL * DD;
    const float* A1 = qp + od;  const float* W1 = kp + od;
    const float* A2 = q2f + od; const float* W2 = k2f + od;
    float* out = attn + (size_t)b * LL * LL;
    const int len = lens[b];

    __shared__ float As[2][8][SMS];
    __shared__ float Bs[2][8][SMS];
    const int tid = threadIdx.x;
    const int tx4 = (tid & 15) << 2;
    const int ty4 = (tid >> 4) << 2;
    const int m0 = blockIdx.y * 128, n0 = blockIdx.x * 128;
    const int lr = tid >> 1;
    const int lk = (tid & 1) << 2;

    const size_t aoff = (size_t)(m0 + lr) * DD + lk;
    const size_t woff = (size_t)(n0 + lr) * DD + lk;

    float acc[8][8] = {};

    {
        float4 a = *(const float4*)(A1 + aoff);
        float4 w = *(const float4*)(W1 + woff);
        As[0][lk+0][lr]=a.x; As[0][lk+1][lr]=a.y; As[0][lk+2][lr]=a.z; As[0][lk+3][lr]=a.w;
        Bs[0][lk+0][lr]=w.x; Bs[0][lk+1][lr]=w.y; Bs[0][lk+2][lr]=w.z; Bs[0][lk+3][lr]=w.w;
    }
    __syncthreads();

    const int nTiles = 64;  // 2 passes * 256/8
    int buf = 0;
    for (int t = 0; t < nTiles; t++) {
        float4 an, bn;
        const bool has = (t + 1 < nTiles);
        if (has) {
            const int tn = t + 1;
            const float* A = (tn < 32) ? A1 : A2;
            const float* W = (tn < 32) ? W1 : W2;
            const int k0 = (tn & 31) * 8;
            an = *(const float4*)(A + aoff + k0);
            bn = *(const float4*)(W + woff + k0);
        }
        mk_step(As[buf], Bs[buf], ty4, tx4, acc);
        if (has) {
            int nb = buf ^ 1;
            As[nb][lk+0][lr]=an.x; As[nb][lk+1][lr]=an.y; As[nb][lk+2][lr]=an.z; As[nb][lk+3][lr]=an.w;
            Bs[nb][lk+0][lr]=bn.x; Bs[nb][lk+1][lr]=bn.y; Bs[nb][lk+2][lr]=bn.z; Bs[nb][lk+3][lr]=bn.w;
            __syncthreads();
            buf = nb;
        }
    }

    #pragma unroll
    for (int i = 0; i < 8; i++) {
        int m = m0 + ty4 + (i & 3) + ((i >> 2) << 6);
        #pragma unroll
        for (int jh = 0; jh < 2; jh++) {
            int nb0 = n0 + jh*64 + tx4;
            float4 v;
            v.x = (nb0+0 < len) ? tanhf(acc[i][jh*4+0] * TEMP_INV) : 0.0f;
            v.y = (nb0+1 < len) ? tanhf(acc[i][jh*4+1] * TEMP_INV) : 0.0f;
            v.z = (nb0+2 < len) ? tanhf(acc[i][jh*4+2] * TEMP_INV) : 0.0f;
            v.w = (nb0+3 < len) ? tanhf(acc[i][jh*4+3] * TEMP_INV) : 0.0f;
            *(float4*)(out + (size_t)m*LL + nb0) = v;
        }
    }
}

// ---------------------------------------------------------------------------
// fa kernel: one block per (b, i): softmax over masked |x_i - x_j| . fi
// ---------------------------------------------------------------------------
__global__ __launch_bounds__(256)
void fa_kernel(const float* __restrict__ x, const float* __restrict__ fi,
               const int* __restrict__ lens, float* __restrict__ fa)
{
    const int bi = blockIdx.x;
    const int b = bi >> 10, i = bi & 1023;
    const int t = threadIdx.x;

    __shared__ float xi[FF], fis[FF];
    __shared__ float red[256];
    if (t < FF) {
        xi[t]  = x[((size_t)b*LL + i)*FF + t];
        fis[t] = fi[t];
    }
    __syncthreads();
    const int len = lens[b];

    float vals[4];
    #pragma unroll
    for (int r = 0; r < 4; r++) {
        int j = t + r*256;
        const float* xj = x + ((size_t)b*LL + j)*FF;
        float s = 0.f;
        #pragma unroll
        for (int f = 0; f < FF; f++) s += fabsf(xi[f] - xj[f]) * fis[f];
        vals[r] = (j < len) ? s : -INFINITY;
    }
    float m = fmaxf(fmaxf(vals[0], vals[1]), fmaxf(vals[2], vals[3]));
    red[t] = m; __syncthreads();
    for (int s = 128; s > 0; s >>= 1) {
        if (t < s) red[t] = fmaxf(red[t], red[t+s]);
        __syncthreads();
    }
    const float rowmax = red[0];
    __syncthreads();
    float e[4], lsum = 0.f;
    #pragma unroll
    for (int r = 0; r < 4; r++) { e[r] = expf(vals[r] - rowmax); lsum += e[r]; }
    red[t] = lsum; __syncthreads();
    for (int s = 128; s > 0; s >>= 1) {
        if (t < s) red[t] += red[t+s];
        __syncthreads();
    }
    const float inv = 1.0f / red[0];
    float* outp = fa + ((size_t)b*LL + i)*LL;
    #pragma unroll
    for (int r = 0; r < 4; r++) outp[t + r*256] = e[r] * inv;
}

// ---------------------------------------------------------------------------
// LayerNorm: one block per row of 256.
// ---------------------------------------------------------------------------
__global__ __launch_bounds__(256)
void ln_kernel(const float* __restrict__ in, const float* __restrict__ gamma,
               const float* __restrict__ beta, float* __restrict__ out)
{
    const int row = blockIdx.x;
    const int t = threadIdx.x;
    __shared__ float red[256];
    const float v = in[(size_t)row*DD + t];
    red[t] = v; __syncthreads();
    for (int s = 128; s > 0; s >>= 1) {
        if (t < s) red[t] += red[t+s];
        __syncthreads();
    }
    const float mean = red[0] * (1.0f/DD);
    __syncthreads();
    const float d = v - mean;
    red[t] = d * d; __syncthreads();
    for (int s = 128; s > 0; s >>= 1) {
        if (t < s) red[t] += red[t+s];
        __syncthreads();
    }
    const float var = red[0] * (1.0f/DD);
    out[(size_t)row*DD + t] = d * rsqrtf(var + LN_EPS) * gamma[t] + beta[t];
}

// ---------------------------------------------------------------------------
// Host launch
// ---------------------------------------------------------------------------
extern "C" void kernel_launch(void* const* d_in, const int* in_sizes, int n_in,
                              void* d_out, int out_size)
{
    int li = -1;
    for (int i = 0; i < n_in; i++) if (in_sizes[i] == BB) { li = i; break; }

    const float* q = (const float*)d_in[0];
    const float* k = (const float*)d_in[1];
    const float* v = (const float*)d_in[2];
    const float* x = (const float*)d_in[3];
    const int* lens;
    const float *w_qs, *w_ks, *w_vs, *w_qs2, *w_ks2, *w_fc, *fi, *gamma, *beta;
    if (li == 4) {
        lens  = (const int*)d_in[4];
        w_qs  = (const float*)d_in[5];  w_ks  = (const float*)d_in[6];
        w_vs  = (const float*)d_in[7];  w_qs2 = (const float*)d_in[8];
        w_ks2 = (const float*)d_in[9];  w_fc  = (const float*)d_in[10];
        fi    = (const float*)d_in[11]; gamma = (const float*)d_in[12];
        beta  = (const float*)d_in[13];
    } else {
        w_qs  = (const float*)d_in[4];  w_ks  = (const float*)d_in[5];
        w_vs  = (const float*)d_in[6];  w_qs2 = (const float*)d_in[7];
        w_ks2 = (const float*)d_in[8];  w_fc  = (const float*)d_in[9];
        fi    = (const float*)d_in[10]; gamma = (const float*)d_in[11];
        beta  = (const float*)d_in[12]; lens  = (const int*)d_in[13];
    }

    float *qp, *kp, *vp, *q2, *k2, *q2f, *k2f, *ov, *fc, *fa, *attn_scratch;
    cudaGetSymbolAddress((void**)&qp,  g_qp);
    cudaGetSymbolAddress((void**)&kp,  g_kp);
    cudaGetSymbolAddress((void**)&vp,  g_vp);
    cudaGetSymbolAddress((void**)&q2,  g_q2);
    cudaGetSymbolAddress((void**)&k2,  g_k2);
    cudaGetSymbolAddress((void**)&q2f, g_q2f);
    cudaGetSymbolAddress((void**)&k2f, g_k2f);
    cudaGetSymbolAddress((void**)&ov,  g_ov);
    cudaGetSymbolAddress((void**)&fc,  g_fc);
    cudaGetSymbolAddress((void**)&fa,  g_fa);
    cudaGetSymbolAddress((void**)&attn_scratch, g_attn_scratch);

    const size_t OUT_ELEMS  = (size_t)BB*LL*DD;
    const size_t ATTN_ELEMS = (size_t)BB*LL*LL;
    float* attn = ((size_t)out_size >= OUT_ELEMS + ATTN_ELEMS)
                ? (float*)d_out + OUT_ELEMS
                : attn_scratch;

    const int M = BB * LL;  // 8192
    dim3 blk(256);

    // 5 projections fused in one launch (z selects which)
    proj_kernel<<<dim3(DD/128, M/128, 5), blk>>>(q, k, v, w_qs, w_ks, w_vs,
                                                 w_qs2, w_ks2, qp, kp, vp, q2, k2);

    // feature-affinity softmax
    fa_kernel<<<M, blk>>>(x, fi, lens, fa);

    // q2f = fa@q2, k2f = fa@k2 (z = b*2+sel)
    bgemm_dual_kernel<<<dim3(DD/128, LL/128, BB*2), blk>>>(fa, q2, k2, q2f, k2f);

    // logits + mask + tanh
    logits_kernel<<<dim3(LL/128, LL/128, BB), blk>>>(qp, kp, q2f, k2f, lens, attn);

    // out = attn @ vp
    bgemm_av_kernel<<<dim3(DD/128, LL/128, BB), blk>>>(attn, vp, ov);

    // fc + residual, then layernorm
    fc_kernel<<<dim3(DD/128, M/128), blk>>>(ov, w_fc, q, fc);
    ln_kernel<<<M, blk>>>(fc, gamma, beta, (float*)d_out);
}

// round 4
// speedup vs baseline: 2.5705x; 2.0028x over previous
#include <cuda_runtime.h>
#include <cuda_bf16.h>
#include <math.h>
#include <stdint.h>

// Problem constants
#define BB 8
#define LL 1024
#define DD 256
#define FF 11
#define TEMP_INV (1.0f/16.0f)
#define LN_EPS 1e-6f

// GEMM config: 128x128 CTA tile, K-slab 64, 8 warps (2m x 4n), warp tile 64x32
#define SLAB 64
#define TB 16384                // one 128x64 bf16 tile
#define BUFB (4*TB)             // AH AL BH BL
#define SMEM_DYN (2*BUFB)       // 131072 (double buffered)

// ---------------------------------------------------------------------------
// Scratch
// ---------------------------------------------------------------------------
__device__ float g_qp [BB*LL*DD];
__device__ float g_kp [BB*LL*DD];
__device__ float g_q2t[BB*LL*DD];   // [b][d][t]
__device__ float g_k2t[BB*LL*DD];
__device__ float g_vpt[BB*LL*DD];
__device__ float g_q2f[BB*LL*DD];
__device__ float g_k2f[BB*LL*DD];
__device__ float g_ov [BB*LL*DD];
__device__ float g_fc [BB*LL*DD];
__device__ float g_fa [(size_t)BB*LL*LL];
__device__ float g_attn_scratch[(size_t)BB*LL*LL];

// ---------------------------------------------------------------------------
// Helpers
// ---------------------------------------------------------------------------
__device__ __forceinline__ uint32_t smem_u32(const void* p) {
    uint32_t a;
    asm("{ .reg .u64 t; cvta.to.shared.u64 t, %1; cvt.u32.u64 %0, t; }"
        : "=r"(a) : "l"(p));
    return a;
}

__device__ __forceinline__ void ldsm_x4(uint32_t* r, uint32_t a) {
    asm volatile("ldmatrix.sync.aligned.m8n8.x4.shared.b16 {%0,%1,%2,%3}, [%4];"
        : "=r"(r[0]), "=r"(r[1]), "=r"(r[2]), "=r"(r[3]) : "r"(a));
}

__device__ __forceinline__ void mma16816(float* c, const uint32_t* a, const uint32_t* b) {
    asm volatile("mma.sync.aligned.m16n8k16.row.col.f32.bf16.bf16.f32 "
        "{%0,%1,%2,%3}, {%4,%5,%6,%7}, {%8,%9}, {%0,%1,%2,%3};"
        : "+f"(c[0]), "+f"(c[1]), "+f"(c[2]), "+f"(c[3])
        : "r"(a[0]), "r"(a[1]), "r"(a[2]), "r"(a[3]), "r"(b[0]), "r"(b[1]));
}

// Load a 128x64 fp32 tile into registers (8 float4 per thread).
__device__ __forceinline__
void ld_tile(const float* __restrict__ src, int r0, int ld, int k0,
             float4* v, int tid)
{
    #pragma unroll
    for (int i = 0; i < 8; i++) {
        int f = tid + (i << 8);
        int row = f >> 4, c4 = f & 15;
        v[i] = *(const float4*)(src + (size_t)(r0 + row) * ld + k0 + (c4 << 2));
    }
}

// Split registers into bf16 hi/lo and store SW128-swizzled into smem.
__device__ __forceinline__
void st_tile(const float4* v, char* smem, uint32_t hiOff, uint32_t loOff, int tid)
{
    #pragma unroll
    for (int i = 0; i < 8; i++) {
        int f = tid + (i << 8);
        int row = f >> 4, c4 = f & 15;
        float4 a = v[i];
        __nv_bfloat162 h01 = __floats2bfloat162_rn(a.x, a.y);
        __nv_bfloat162 h23 = __floats2bfloat162_rn(a.z, a.w);
        float rx = a.x - __bfloat162float(h01.x);
        float ry = a.y - __bfloat162float(h01.y);
        float rz = a.z - __bfloat162float(h23.x);
        float rw = a.w - __bfloat162float(h23.y);
        __nv_bfloat162 l01 = __floats2bfloat162_rn(rx, ry);
        __nv_bfloat162 l23 = __floats2bfloat162_rn(rz, rw);
        uint32_t byte = (row << 7) + (c4 << 3);
        uint32_t sw = byte ^ ((byte >> 3) & 0x70);
        *(uint2*)(smem + hiOff + sw) = make_uint2(*(uint32_t*)&h01, *(uint32_t*)&h23);
        *(uint2*)(smem + loOff + sw) = make_uint2(*(uint32_t*)&l01, *(uint32_t*)&l23);
    }
}

// ---------------------------------------------------------------------------
// bf16x3 mma.sync GEMM body. NT: C[m,n] = sum_k A[m,k]*B[n,k] over (A1,B1,k1)
// then (A2,B2,k2). MODE: 0 plain, 1 +add residual, 2 tanh(acc/16) w/ col mask
// ---------------------------------------------------------------------------
template<int MODE>
__device__ __forceinline__
void tc_body(const float* __restrict__ A1, const float* __restrict__ B1, int k1,
             const float* __restrict__ A2, const float* __restrict__ B2, int k2,
             float* __restrict__ C, const float* __restrict__ add,
             int ldc, int len, int m0, int n0)
{
    extern __shared__ char smem[];
    const uint32_t sb = smem_u32(smem);
    const int tid = threadIdx.x;
    const int lane = tid & 31, wid = tid >> 5;
    const int wm = wid & 1, wn = wid >> 1;

    float acc[4][4][4] = {};

    // ldmatrix lane addressing
    // A frags: lanes 0-15 rows m0..15 @kb, lanes 16-31 rows m0..15 @kb+16B
    const int a_row = wm * 64 + (lane & 15);
    const uint32_t a_colp = (lane >> 4) << 4;
    const uint32_t a_xor = (uint32_t)(a_row & 7) << 4;
    // B frags: per 16-row pair: lanes>>4 selects n8 tile, lanes>>3&1 selects k half
    const int b_row = wn * 32 + ((lane >> 4) << 3) + (lane & 7);
    const uint32_t b_colp = ((lane >> 3) & 1) << 4;
    const uint32_t b_xor = (uint32_t)(b_row & 7) << 4;

    const int n1 = k1 / SLAB;
    const int nslabs = n1 + (A2 ? k2 / SLAB : 0);

    float4 av[8], bv[8];
    // prologue: slab 0
    ld_tile(A1, m0, k1, 0, av, tid);
    ld_tile(B1, n0, k1, 0, bv, tid);
    st_tile(av, smem, 0, TB, tid);
    st_tile(bv, smem, 2*TB, 3*TB, tid);
    __syncthreads();

    for (int s = 0; s < nslabs; s++) {
        const uint32_t bo = (s & 1) * BUFB;
        const uint32_t bn = bo ^ BUFB;
        const bool has = (s + 1) < nslabs;
        const float *An = A1, *Bn = B1; int ldn = k1, k0n = 0;
        if (has) {
            int sn = s + 1;
            if (sn < n1) { An = A1; Bn = B1; ldn = k1; k0n = sn * SLAB; }
            else         { An = A2; Bn = B2; ldn = k2; k0n = (sn - n1) * SLAB; }
        }

        #pragma unroll
        for (int kk = 0; kk < 4; kk++) {
            if (kk == 0 && has) ld_tile(An, m0, ldn, k0n, av, tid);
            if (kk == 2 && has) {
                st_tile(av, smem, bn, bn + TB, tid);
                ld_tile(Bn, n0, ldn, k0n, bv, tid);
            }
            if (kk == 3 && has) st_tile(bv, smem, bn + 2*TB, bn + 3*TB, tid);

            const uint32_t kb = kk << 5;
            uint32_t bH[8], bL[8];
            {
                uint32_t r = (uint32_t)b_row << 7;
                uint32_t c = (kb + b_colp) ^ b_xor;
                ldsm_x4(bH + 0, sb + bo + 2*TB + r + c);
                ldsm_x4(bH + 4, sb + bo + 2*TB + r + 2048 + c);
                ldsm_x4(bL + 0, sb + bo + 3*TB + r + c);
                ldsm_x4(bL + 4, sb + bo + 3*TB + r + 2048 + c);
            }
            #pragma unroll
            for (int mt = 0; mt < 4; mt++) {
                uint32_t aH[4], aL[4];
                uint32_t r = (uint32_t)(a_row + mt*16) << 7;
                uint32_t c = (kb + a_colp) ^ a_xor;
                ldsm_x4(aH, sb + bo + r + c);
                ldsm_x4(aL, sb + bo + TB + r + c);
                #pragma unroll
                for (int nt = 0; nt < 4; nt++) {
                    mma16816(acc[mt][nt], aH, bH + nt*2);
                    mma16816(acc[mt][nt], aH, bL + nt*2);
                    mma16816(acc[mt][nt], aL, bH + nt*2);
                }
            }
        }
        if (has) __syncthreads();
    }

    // epilogue
    const int mg = m0 + wm * 64;
    const int ng = n0 + wn * 32;
    const int rq = lane >> 2;
    const int cq = (lane & 3) << 1;
    #pragma unroll
    for (int mt = 0; mt < 4; mt++) {
        #pragma unroll
        for (int nt = 0; nt < 4; nt++) {
            const float* a4 = acc[mt][nt];
            const int r0 = mg + mt*16 + rq, r1 = r0 + 8;
            const int c0 = ng + nt*8 + cq;
            if (MODE == 0) {
                *(float2*)(C + (size_t)r0*ldc + c0) = make_float2(a4[0], a4[1]);
                *(float2*)(C + (size_t)r1*ldc + c0) = make_float2(a4[2], a4[3]);
            } else if (MODE == 1) {
                float2 x0 = *(const float2*)(add + (size_t)r0*ldc + c0);
                float2 x1 = *(const float2*)(add + (size_t)r1*ldc + c0);
                *(float2*)(C + (size_t)r0*ldc + c0) = make_float2(a4[0]+x0.x, a4[1]+x0.y);
                *(float2*)(C + (size_t)r1*ldc + c0) = make_float2(a4[2]+x1.x, a4[3]+x1.y);
            } else {
                float2 v0, v1;
                v0.x = (c0   < len) ? tanhf(a4[0]*TEMP_INV) : 0.f;
                v0.y = (c0+1 < len) ? tanhf(a4[1]*TEMP_INV) : 0.f;
                v1.x = (c0   < len) ? tanhf(a4[2]*TEMP_INV) : 0.f;
                v1.y = (c0+1 < len) ? tanhf(a4[3]*TEMP_INV) : 0.f;
                *(float2*)(C + (size_t)r0*ldc + c0) = v0;
                *(float2*)(C + (size_t)r1*ldc + c0) = v1;
            }
        }
    }
}

// ---------------------------------------------------------------------------
// Stage kernels
// ---------------------------------------------------------------------------
__global__ __launch_bounds__(256, 1)
void tc_proj_qk(const float* __restrict__ q, const float* __restrict__ k,
                const float* __restrict__ w_qs, const float* __restrict__ w_ks,
                float* __restrict__ qp, float* __restrict__ kp)
{
    const int m0 = blockIdx.y * 128, n0 = blockIdx.x * 128;
    if (blockIdx.z == 0)
        tc_body<0>(q, w_qs, DD, nullptr, nullptr, 0, qp, nullptr, DD, 0, m0, n0);
    else
        tc_body<0>(k, w_ks, DD, nullptr, nullptr, 0, kp, nullptr, DD, 0, m0, n0);
}

// Transposed projections: C_b = W (256xK) . X_b^T -> [256,1024] = [d][t]
__global__ __launch_bounds__(256, 1)
void tc_projT(const float* __restrict__ q, const float* __restrict__ k,
              const float* __restrict__ v,
              const float* __restrict__ w_qs2, const float* __restrict__ w_ks2,
              const float* __restrict__ w_vs,
              float* __restrict__ q2t, float* __restrict__ k2t,
              float* __restrict__ vpt)
{
    const int b = blockIdx.z / 3, w = blockIdx.z % 3;
    const int m0 = blockIdx.y * 128, n0 = blockIdx.x * 128;
    const float* W; const float* X; float* C;
    if      (w == 0) { W = w_qs2; X = q; C = q2t; }
    else if (w == 1) { W = w_ks2; X = k; C = k2t; }
    else             { W = w_vs;  X = v; C = vpt; }
    tc_body<0>(W, X + (size_t)b*LL*DD, DD, nullptr, nullptr, 0,
               C + (size_t)b*DD*LL, nullptr, LL, 0, m0, n0);
}

// q2f = fa @ q2  (as NT with q2t), k2f = fa @ k2
__global__ __launch_bounds__(256, 1)
void tc_dual(const float* __restrict__ fa, const float* __restrict__ q2t,
             const float* __restrict__ k2t,
             float* __restrict__ q2f, float* __restrict__ k2f)
{
    const int b = blockIdx.z >> 1, sel = blockIdx.z & 1;
    const int m0 = blockIdx.y * 128, n0 = blockIdx.x * 128;
    const float* A = fa + (size_t)b * LL * LL;
    const float* B = (sel ? k2t : q2t) + (size_t)b * DD * LL;
    float* C = (sel ? k2f : q2f) + (size_t)b * LL * DD;
    tc_body<0>(A, B, LL, nullptr, nullptr, 0, C, nullptr, DD, 0, m0, n0);
}

__global__ __launch_bounds__(256, 1)
void tc_logits(const float* __restrict__ qp, const float* __restrict__ kp,
               const float* __restrict__ q2f, const float* __restrict__ k2f,
               const int* __restrict__ lens, float* __restrict__ attn)
{
    const int b = blockIdx.z;
    const size_t od = (size_t)b * LL * DD;
    const int m0 = blockIdx.y * 128, n0 = blockIdx.x * 128;
    tc_body<2>(qp + od, kp + od, DD, q2f + od, k2f + od, DD,
               attn + (size_t)b * LL * LL, nullptr, LL, lens[b], m0, n0);
}

__global__ __launch_bounds__(256, 1)
void tc_av(const float* __restrict__ attn, const float* __restrict__ vpt,
           float* __restrict__ ov)
{
    const int b = blockIdx.z;
    const int m0 = blockIdx.y * 128, n0 = blockIdx.x * 128;
    tc_body<0>(attn + (size_t)b * LL * LL, vpt + (size_t)b * DD * LL, LL,
               nullptr, nullptr, 0, ov + (size_t)b * LL * DD, nullptr, DD, 0, m0, n0);
}

__global__ __launch_bounds__(256, 1)
void tc_fc(const float* __restrict__ ov, const float* __restrict__ w_fc,
           const float* __restrict__ q, float* __restrict__ out)
{
    const int m0 = blockIdx.y * 128, n0 = blockIdx.x * 128;
    tc_body<1>(ov, w_fc, DD, nullptr, nullptr, 0, out, q, DD, 0, m0, n0);
}

// ---------------------------------------------------------------------------
// fa kernel: softmax over masked |x_i - x_j| . fi  (one block per (b,i))
// ---------------------------------------------------------------------------
__global__ __launch_bounds__(256)
void fa_kernel(const float* __restrict__ x, const float* __restrict__ fi,
               const int* __restrict__ lens, float* __restrict__ fa)
{
    const int bi = blockIdx.x;
    const int b = bi >> 10, i = bi & 1023;
    const int t = threadIdx.x;

    __shared__ float xi[FF], fis[FF];
    __shared__ float red[256];
    if (t < FF) {
        xi[t]  = x[((size_t)b*LL + i)*FF + t];
        fis[t] = fi[t];
    }
    __syncthreads();
    const int len = lens[b];

    float vals[4];
    #pragma unroll
    for (int r = 0; r < 4; r++) {
        int j = t + r*256;
        const float* xj = x + ((size_t)b*LL + j)*FF;
        float s = 0.f;
        #pragma unroll
        for (int f = 0; f < FF; f++) s += fabsf(xi[f] - xj[f]) * fis[f];
        vals[r] = (j < len) ? s : -INFINITY;
    }
    float m = fmaxf(fmaxf(vals[0], vals[1]), fmaxf(vals[2], vals[3]));
    red[t] = m; __syncthreads();
    for (int s = 128; s > 0; s >>= 1) {
        if (t < s) red[t] = fmaxf(red[t], red[t+s]);
        __syncthreads();
    }
    const float rowmax = red[0];
    __syncthreads();
    float e[4], lsum = 0.f;
    #pragma unroll
    for (int r = 0; r < 4; r++) { e[r] = expf(vals[r] - rowmax); lsum += e[r]; }
    red[t] = lsum; __syncthreads();
    for (int s = 128; s > 0; s >>= 1) {
        if (t < s) red[t] += red[t+s];
        __syncthreads();
    }
    const float inv = 1.0f / red[0];
    float* outp = fa + ((size_t)b*LL + i)*LL;
    #pragma unroll
    for (int r = 0; r < 4; r++) outp[t + r*256] = e[r] * inv;
}

// ---------------------------------------------------------------------------
// LayerNorm
// ---------------------------------------------------------------------------
__global__ __launch_bounds__(256)
void ln_kernel(const float* __restrict__ in, const float* __restrict__ gamma,
               const float* __restrict__ beta, float* __restrict__ out)
{
    const int row = blockIdx.x;
    const int t = threadIdx.x;
    __shared__ float red[256];
    const float v = in[(size_t)row*DD + t];
    red[t] = v; __syncthreads();
    for (int s = 128; s > 0; s >>= 1) {
        if (t < s) red[t] += red[t+s];
        __syncthreads();
    }
    const float mean = red[0] * (1.0f/DD);
    __syncthreads();
    const float d = v - mean;
    red[t] = d * d; __syncthreads();
    for (int s = 128; s > 0; s >>= 1) {
        if (t < s) red[t] += red[t+s];
        __syncthreads();
    }
    const float var = red[0] * (1.0f/DD);
    out[(size_t)row*DD + t] = d * rsqrtf(var + LN_EPS) * gamma[t] + beta[t];
}

// ---------------------------------------------------------------------------
// Host launch
// ---------------------------------------------------------------------------
extern "C" void kernel_launch(void* const* d_in, const int* in_sizes, int n_in,
                              void* d_out, int out_size)
{
    int li = -1;
    for (int i = 0; i < n_in; i++) if (in_sizes[i] == BB) { li = i; break; }

    const float* q = (const float*)d_in[0];
    const float* k = (const float*)d_in[1];
    const float* v = (const float*)d_in[2];
    const float* x = (const float*)d_in[3];
    const int* lens;
    const float *w_qs, *w_ks, *w_vs, *w_qs2, *w_ks2, *w_fc, *fi, *gamma, *beta;
    if (li == 4) {
        lens  = (const int*)d_in[4];
        w_qs  = (const float*)d_in[5];  w_ks  = (const float*)d_in[6];
        w_vs  = (const float*)d_in[7];  w_qs2 = (const float*)d_in[8];
        w_ks2 = (const float*)d_in[9];  w_fc  = (const float*)d_in[10];
        fi    = (const float*)d_in[11]; gamma = (const float*)d_in[12];
        beta  = (const float*)d_in[13];
    } else {
        w_qs  = (const float*)d_in[4];  w_ks  = (const float*)d_in[5];
        w_vs  = (const float*)d_in[6];  w_qs2 = (const float*)d_in[7];
        w_ks2 = (const float*)d_in[8];  w_fc  = (const float*)d_in[9];
        fi    = (const float*)d_in[10]; gamma = (const float*)d_in[11];
        beta  = (const float*)d_in[12]; lens  = (const int*)d_in[13];
    }

    float *qp, *kp, *q2t, *k2t, *vpt, *q2f, *k2f, *ov, *fc, *fa, *attn_scratch;
    cudaGetSymbolAddress((void**)&qp,  g_qp);
    cudaGetSymbolAddress((void**)&kp,  g_kp);
    cudaGetSymbolAddress((void**)&q2t, g_q2t);
    cudaGetSymbolAddress((void**)&k2t, g_k2t);
    cudaGetSymbolAddress((void**)&vpt, g_vpt);
    cudaGetSymbolAddress((void**)&q2f, g_q2f);
    cudaGetSymbolAddress((void**)&k2f, g_k2f);
    cudaGetSymbolAddress((void**)&ov,  g_ov);
    cudaGetSymbolAddress((void**)&fc,  g_fc);
    cudaGetSymbolAddress((void**)&fa,  g_fa);
    cudaGetSymbolAddress((void**)&attn_scratch, g_attn_scratch);

    const size_t OUT_ELEMS  = (size_t)BB*LL*DD;
    const size_t ATTN_ELEMS = (size_t)BB*LL*LL;
    float* attn = ((size_t)out_size >= OUT_ELEMS + ATTN_ELEMS)
                ? (float*)d_out + OUT_ELEMS
                : attn_scratch;

    cudaFuncSetAttribute(tc_proj_qk, cudaFuncAttributeMaxDynamicSharedMemorySize, SMEM_DYN);
    cudaFuncSetAttribute(tc_projT,   cudaFuncAttributeMaxDynamicSharedMemorySize, SMEM_DYN);
    cudaFuncSetAttribute(tc_dual,    cudaFuncAttributeMaxDynamicSharedMemorySize, SMEM_DYN);
    cudaFuncSetAttribute(tc_logits,  cudaFuncAttributeMaxDynamicSharedMemorySize, SMEM_DYN);
    cudaFuncSetAttribute(tc_av,      cudaFuncAttributeMaxDynamicSharedMemorySize, SMEM_DYN);
    cudaFuncSetAttribute(tc_fc,      cudaFuncAttributeMaxDynamicSharedMemorySize, SMEM_DYN);

    const int M = BB * LL;  // 8192
    dim3 blk(256);

    // qp, kp projections: [8192,256] x [256,256]
    tc_proj_qk<<<dim3(DD/128, M/128, 2), blk, SMEM_DYN>>>(q, k, w_qs, w_ks, qp, kp);

    // transposed projections q2t/k2t/vpt: per batch [256,256] x [1024,256]^T
    tc_projT<<<dim3(LL/128, DD/128, 3*BB), blk, SMEM_DYN>>>(
        q, k, v, w_qs2, w_ks2, w_vs, q2t, k2t, vpt);

    // feature-affinity softmax
    fa_kernel<<<M, blk>>>(x, fi, lens, fa);

    // q2f = fa@q2, k2f = fa@k2
    tc_dual<<<dim3(DD/128, LL/128, BB*2), blk, SMEM_DYN>>>(fa, q2t, k2t, q2f, k2f);

    // logits + mask + tanh
    tc_logits<<<dim3(LL/128, LL/128, BB), blk, SMEM_DYN>>>(qp, kp, q2f, k2f, lens, attn);

    // out = attn @ vp
    tc_av<<<dim3(DD/128, LL/128, BB), blk, SMEM_DYN>>>(attn, vpt, ov);

    // fc + residual, then layernorm
    tc_fc<<<dim3(DD/128, M/128, 1), blk, SMEM_DYN>>>(ov, w_fc, q, fc);
    ln_kernel<<<M, blk>>>(fc, gamma, beta, (float*)d_out);
}